// round 17
// baseline (speedup 1.0000x reference)
#include <cuda_runtime.h>
#include <cuda_bf16.h>
#include <math.h>
#include <cstdint>

#define N_NODES 50000
#define N_EDGES 1600000
#define IN_C 512
#define HID_C 256
#define OUT_C 50
#define HSTRIDE 64
#define NUM_LAYERS 10
#define ALPHA 0.1f

// ---------------- scratch (device-code-only symbols) ----------------
__device__ float      g_x0[(size_t)N_NODES * HSTRIDE];
__device__ float      g_hA[(size_t)N_NODES * HSTRIDE];
__device__ float      g_hB[(size_t)N_NODES * HSTRIDE];
__device__ int        g_deg[N_NODES];
__device__ int        g_rowptr[N_NODES + 1];
__device__ int        g_cursor[N_NODES];
__device__ long long  g_csr[N_EDGES];

// ---------------------------- CSR build -----------------------------------
__global__ void zero_deg_kernel() {
    int i = blockIdx.x * blockDim.x + threadIdx.x;
    if (i < N_NODES) g_deg[i] = 0;
}
__global__ void hist_kernel(const int* __restrict__ erow) {
    int e = blockIdx.x * blockDim.x + threadIdx.x;
    if (e < N_EDGES) {
        unsigned r = (unsigned)erow[e];
        if (r < N_NODES) atomicAdd(&g_deg[r], 1);
    }
}
__global__ void scan_kernel() {
    __shared__ int sh[1024];
    const int PER = (N_NODES + 1023) / 1024;
    int t = threadIdx.x;
    int base = t * PER;
    int sum = 0;
    for (int i = 0; i < PER; i++) {
        int idx = base + i;
        if (idx < N_NODES) sum += g_deg[idx];
    }
    sh[t] = sum;
    __syncthreads();
    for (int off = 1; off < 1024; off <<= 1) {
        int add = (t >= off) ? sh[t - off] : 0;
        __syncthreads();
        sh[t] += add;
        __syncthreads();
    }
    int excl = sh[t] - sum;
    int run = excl;
    for (int i = 0; i < PER; i++) {
        int idx = base + i;
        if (idx < N_NODES) {
            g_rowptr[idx] = run;
            g_cursor[idx] = run;
            run += g_deg[idx];
        }
    }
    if (t == 1023) g_rowptr[N_NODES] = excl + sum;
}
__global__ void scatter_kernel(const int* __restrict__ erow,
                               const int* __restrict__ ecol,
                               const float* __restrict__ ew) {
    int e = blockIdx.x * blockDim.x + threadIdx.x;
    if (e >= N_EDGES) return;
    unsigned r = (unsigned)erow[e];
    if (r >= N_NODES) return;
    int pos = atomicAdd(&g_cursor[r], 1);
    long long packed = ((long long)__float_as_int(ew[e]) << 32) | (unsigned int)ecol[e];
    g_csr[pos] = packed;
}

// ---------------- fused MLP via mma.sync bf16 hi/lo split -------------------
// Stage 1: h1 = relu(X @ W1 + b1)  [64 x 256 per block]  (acc in regs)
// Stage 2: x0 = h1 @ W2 + b2      [64 x 50 per block]   (h1 via SMEM bf16)
#define ASTRW 20     // A smem: 32 k = 16 words + 4 pad
#define BSTRW 136    // B smem: 256 n = 128 words + 8 pad
#define HSTRW 132    // H smem: 256 k = 128 words + 4 pad
#define WSTRW 32     // W2 smem: 56 n = 28 words + 4 pad
#define S1_WORDS (64 * ASTRW * 2 + 32 * BSTRW * 2)          // 11264
#define S2_WORDS (64 * HSTRW * 2 + 256 * WSTRW * 2)         // 33280
#define FUSED_SMEM (S2_WORDS * 4)                           // 133120 B

__device__ __forceinline__ uint32_t smem_addr_u32(const void* p) {
    uint32_t a;
    asm("{ .reg .u64 t; cvta.to.shared.u64 t, %1; cvt.u32.u64 %0, t; }"
        : "=r"(a) : "l"(p));
    return a;
}
__device__ __forceinline__ void ldsm_x4(uint32_t* r, uint32_t addr) {
    asm volatile("ldmatrix.sync.aligned.m8n8.x4.shared.b16 {%0,%1,%2,%3}, [%4];"
                 : "=r"(r[0]), "=r"(r[1]), "=r"(r[2]), "=r"(r[3]) : "r"(addr));
}
__device__ __forceinline__ void ldsm_x2t(uint32_t* r, uint32_t addr) {
    asm volatile("ldmatrix.sync.aligned.m8n8.x2.trans.shared.b16 {%0,%1}, [%2];"
                 : "=r"(r[0]), "=r"(r[1]) : "r"(addr));
}
__device__ __forceinline__ void mma_bf16(float* d, const uint32_t* a, const uint32_t* b) {
    asm volatile("mma.sync.aligned.m16n8k16.row.col.f32.bf16.bf16.f32 "
                 "{%0,%1,%2,%3}, {%4,%5,%6,%7}, {%8,%9}, {%0,%1,%2,%3};"
                 : "+f"(d[0]), "+f"(d[1]), "+f"(d[2]), "+f"(d[3])
                 : "r"(a[0]), "r"(a[1]), "r"(a[2]), "r"(a[3]), "r"(b[0]), "r"(b[1]));
}
__device__ __forceinline__ uint32_t pack_bf16_hi(float x, float y) {
    __nv_bfloat16 hx = __float2bfloat16(x);
    __nv_bfloat16 hy = __float2bfloat16(y);
    return ((uint32_t)__bfloat16_as_ushort(hy) << 16) | __bfloat16_as_ushort(hx);
}
__device__ __forceinline__ uint32_t pack_bf16_lo(float x, float y) {
    __nv_bfloat16 hx = __float2bfloat16(x);
    __nv_bfloat16 hy = __float2bfloat16(y);
    __nv_bfloat16 lx = __float2bfloat16(x - __bfloat162float(hx));
    __nv_bfloat16 ly = __float2bfloat16(y - __bfloat162float(hy));
    return ((uint32_t)__bfloat16_as_ushort(ly) << 16) | __bfloat16_as_ushort(lx);
}

__global__ void __launch_bounds__(256) mlp_fused_kernel(
        const float* __restrict__ X, const float* __restrict__ W1,
        const float* __restrict__ b1, const float* __restrict__ W2,
        const float* __restrict__ b2) {
    extern __shared__ uint32_t sm[];
    // stage-1 overlay
    uint32_t* Ah = sm;
    uint32_t* Al = Ah + 64 * ASTRW;
    uint32_t* Bh = Al + 64 * ASTRW;
    uint32_t* Bl = Bh + 32 * BSTRW;
    // stage-2 overlay (same memory, used strictly after stage 1)
    uint32_t* Hh = sm;
    uint32_t* Hl = Hh + 64 * HSTRW;
    uint32_t* Wh = Hl + 64 * HSTRW;
    uint32_t* Wl = Wh + 256 * WSTRW;

    int tid = threadIdx.x;
    int wid = tid >> 5;
    int lane = tid & 31;
    int wm = wid >> 2;          // 0..1 : 32-row group
    int wn = wid & 3;           // 0..3 : 64-col group
    int bm = blockIdx.x * 64;

    float d[2][8][4];
    #pragma unroll
    for (int i = 0; i < 2; i++)
        #pragma unroll
        for (int j = 0; j < 8; j++)
            #pragma unroll
            for (int q = 0; q < 4; q++) d[i][j][q] = 0.f;

    const uint32_t AhB = smem_addr_u32(Ah);
    const uint32_t AlB = smem_addr_u32(Al);
    const uint32_t BhB = smem_addr_u32(Bh);
    const uint32_t BlB = smem_addr_u32(Bl);

    // staging indices
    int s_arow = tid >> 2;              // 0..63
    int s_ak = (tid & 3) * 8;           // 0,8,16,24
    int s_grow = bm + s_arow;
    int s_bk = tid >> 3;                // 0..31
    int s_bn = (tid & 7) * 32;          // 0..224

    // ldmatrix lane addressing (validated in R15)
    int lm_row = ((lane >> 3) & 1) * 8 + (lane & 7);
    int lm_kofs = (lane >> 4) * 8;
    int lb_row = (((lane & 15) >> 3)) * 8 + (lane & 7);

    // ---------------- stage 1: X @ W1 ----------------
    for (int c = 0; c < IN_C / 32; c++) {
        int k0 = c * 32;
        {   // A: X[bm..bm+63][k0..k0+31]
            const float* src = X + (size_t)s_grow * IN_C + k0 + s_ak;
            #pragma unroll
            for (int f = 0; f < 2; f++) {
                float4 v = make_float4(0.f, 0.f, 0.f, 0.f);
                if (s_grow < N_NODES) v = *(const float4*)(src + f * 4);
                int w = s_arow * ASTRW + ((s_ak + f * 4) >> 1);
                Ah[w]     = pack_bf16_hi(v.x, v.y);
                Ah[w + 1] = pack_bf16_hi(v.z, v.w);
                Al[w]     = pack_bf16_lo(v.x, v.y);
                Al[w + 1] = pack_bf16_lo(v.z, v.w);
            }
        }
        {   // B: W1[k0+k][0..255]
            const float* src = W1 + (size_t)(k0 + s_bk) * HID_C + s_bn;
            #pragma unroll
            for (int f = 0; f < 8; f++) {
                float4 v = *(const float4*)(src + f * 4);
                int w = s_bk * BSTRW + ((s_bn + f * 4) >> 1);
                Bh[w]     = pack_bf16_hi(v.x, v.y);
                Bh[w + 1] = pack_bf16_hi(v.z, v.w);
                Bl[w]     = pack_bf16_lo(v.x, v.y);
                Bl[w + 1] = pack_bf16_lo(v.z, v.w);
            }
        }
        __syncthreads();

        #pragma unroll
        for (int ks = 0; ks < 2; ks++) {
            uint32_t ah[2][4], al[2][4], bh[8][2], bl[8][2];
            #pragma unroll
            for (int mt = 0; mt < 2; mt++) {
                int row = wm * 32 + mt * 16 + lm_row;
                uint32_t off = (uint32_t)(row * ASTRW + ((ks * 16 + lm_kofs) >> 1)) * 4u;
                ldsm_x4(ah[mt], AhB + off);
                ldsm_x4(al[mt], AlB + off);
            }
            #pragma unroll
            for (int nt = 0; nt < 8; nt++) {
                int krow = ks * 16 + lb_row;
                int ncol = wn * 64 + nt * 8;
                uint32_t off = (uint32_t)(krow * BSTRW + (ncol >> 1)) * 4u;
                ldsm_x2t(bh[nt], BhB + off);
                ldsm_x2t(bl[nt], BlB + off);
            }
            #pragma unroll
            for (int mt = 0; mt < 2; mt++)
                #pragma unroll
                for (int nt = 0; nt < 8; nt++) {
                    mma_bf16(d[mt][nt], ah[mt], bh[nt]);
                    mma_bf16(d[mt][nt], ah[mt], bl[nt]);
                    mma_bf16(d[mt][nt], al[mt], bh[nt]);
                }
        }
        __syncthreads();
    }

    // ---------------- epilogue 1: bias+relu -> H (bf16 hi/lo in SMEM) -------
    int g = lane >> 2;
    int tg = lane & 3;
    #pragma unroll
    for (int mt = 0; mt < 2; mt++) {
        int r0 = wm * 32 + mt * 16 + g;      // local rows
        int r1 = r0 + 8;
        #pragma unroll
        for (int nt = 0; nt < 8; nt++) {
            int n = wn * 64 + nt * 8 + tg * 2;
            float2 bb = *(const float2*)&b1[n];
            float ox0 = fmaxf(d[mt][nt][0] + bb.x, 0.f);
            float oy0 = fmaxf(d[mt][nt][1] + bb.y, 0.f);
            float ox1 = fmaxf(d[mt][nt][2] + bb.x, 0.f);
            float oy1 = fmaxf(d[mt][nt][3] + bb.y, 0.f);
            Hh[r0 * HSTRW + (n >> 1)] = pack_bf16_hi(ox0, oy0);
            Hl[r0 * HSTRW + (n >> 1)] = pack_bf16_lo(ox0, oy0);
            Hh[r1 * HSTRW + (n >> 1)] = pack_bf16_hi(ox1, oy1);
            Hl[r1 * HSTRW + (n >> 1)] = pack_bf16_lo(ox1, oy1);
        }
    }
    // ---------------- stage W2 into SMEM (k=tid row) ------------------------
    {
        const float* src = W2 + (size_t)tid * OUT_C;
        #pragma unroll
        for (int w = 0; w < 25; w++) {
            float a = src[2 * w], b = src[2 * w + 1];
            Wh[tid * WSTRW + w] = pack_bf16_hi(a, b);
            Wl[tid * WSTRW + w] = pack_bf16_lo(a, b);
        }
        Wh[tid * WSTRW + 25] = 0u; Wh[tid * WSTRW + 26] = 0u; Wh[tid * WSTRW + 27] = 0u;
        Wl[tid * WSTRW + 25] = 0u; Wl[tid * WSTRW + 26] = 0u; Wl[tid * WSTRW + 27] = 0u;
    }
    __syncthreads();

    // ---------------- stage 2: h1 @ W2 (warps 0..3, 16 rows each) -----------
    if (wid < 4) {
        const uint32_t HhB = smem_addr_u32(Hh);
        const uint32_t HlB = smem_addr_u32(Hl);
        const uint32_t WhB = smem_addr_u32(Wh);
        const uint32_t WlB = smem_addr_u32(Wl);
        float d2[7][4];
        #pragma unroll
        for (int j = 0; j < 7; j++)
            #pragma unroll
            for (int q = 0; q < 4; q++) d2[j][q] = 0.f;

        #pragma unroll
        for (int ks = 0; ks < 16; ks++) {
            int k = ks * 16;
            uint32_t ah[4], al[4];
            int row = wid * 16 + lm_row;
            uint32_t offA = (uint32_t)(row * HSTRW + ((k + lm_kofs) >> 1)) * 4u;
            ldsm_x4(ah, HhB + offA);
            ldsm_x4(al, HlB + offA);
            #pragma unroll
            for (int nt = 0; nt < 7; nt++) {
                uint32_t bh[2], bl[2];
                uint32_t offB = (uint32_t)((k + lb_row) * WSTRW + nt * 4) * 4u;
                ldsm_x2t(bh, WhB + offB);
                ldsm_x2t(bl, WlB + offB);
                mma_bf16(d2[nt], ah, bh);
                mma_bf16(d2[nt], ah, bl);
                mma_bf16(d2[nt], al, bh);
            }
        }
        // epilogue 2: + b2 -> g_x0, g_hA (stride-64 rows)
        int grow0 = bm + wid * 16 + g;
        int grow1 = grow0 + 8;
        #pragma unroll
        for (int nt = 0; nt < 7; nt++) {
            int n = nt * 8 + tg * 2;
            if (n < OUT_C) {
                float2 bb = *(const float2*)&b2[n];
                if (grow0 < N_NODES) {
                    float2 o = make_float2(d2[nt][0] + bb.x, d2[nt][1] + bb.y);
                    *(float2*)&g_x0[((size_t)grow0 << 6) + n] = o;
                    *(float2*)&g_hA[((size_t)grow0 << 6) + n] = o;
                }
                if (grow1 < N_NODES) {
                    float2 o = make_float2(d2[nt][2] + bb.x, d2[nt][3] + bb.y);
                    *(float2*)&g_x0[((size_t)grow1 << 6) + n] = o;
                    *(float2*)&g_hA[((size_t)grow1 << 6) + n] = o;
                }
            }
        }
    }
}

// ------------------------------ SpMM ---------------------------------------
__global__ void __launch_bounds__(256) spmm_kernel(int flip) {
    const float* __restrict__ hsrc = flip ? g_hB : g_hA;
    float* __restrict__       hdst = flip ? g_hA : g_hB;

    int row = (blockIdx.x * blockDim.x + threadIdx.x) >> 5;
    int lane = threadIdx.x & 31;
    if (row >= N_NODES) return;
    int start = g_rowptr[row];
    int end = g_rowptr[row + 1];

    float acc0 = 0.f, acc1 = 0.f;
    for (int e0 = start; e0 < end; e0 += 32) {
        long long p = 0;
        int e = e0 + lane;
        if (e < end) p = g_csr[e];
        int n = min(32, end - e0);
        for (int j = 0; j < n; j++) {
            long long pj = __shfl_sync(0xffffffffu, p, j);
            int col = (int)((unsigned long long)pj & 0xffffffffull);
            float w = __int_as_float((int)((unsigned long long)pj >> 32));
            const float* hr = hsrc + ((size_t)col << 6);
            acc0 = fmaf(w, hr[lane], acc0);
            if (lane < OUT_C - 32) acc1 = fmaf(w, hr[32 + lane], acc1);
        }
    }
    const float* x0r = g_x0 + ((size_t)row << 6);
    float* outp = hdst + ((size_t)row << 6);
    outp[lane] = (1.0f - ALPHA) * acc0 + ALPHA * x0r[lane];
    if (lane < OUT_C - 32)
        outp[32 + lane] = (1.0f - ALPHA) * acc1 + ALPHA * x0r[32 + lane];
}

// ---------------------------- log_softmax ----------------------------------
__global__ void __launch_bounds__(256) lsm_kernel(float* __restrict__ out) {
    int row = (blockIdx.x * blockDim.x + threadIdx.x) >> 5;
    int lane = threadIdx.x & 31;
    if (row >= N_NODES) return;
    const float* hr = g_hA + ((size_t)row << 6);
    float v0 = hr[lane];
    float v1 = (lane < OUT_C - 32) ? hr[32 + lane] : -INFINITY;

    float m = fmaxf(v0, v1);
    #pragma unroll
    for (int o = 16; o > 0; o >>= 1)
        m = fmaxf(m, __shfl_xor_sync(0xffffffffu, m, o));

    float s = expf(v0 - m) + ((lane < OUT_C - 32) ? expf(v1 - m) : 0.f);
    #pragma unroll
    for (int o = 16; o > 0; o >>= 1)
        s += __shfl_xor_sync(0xffffffffu, s, o);

    float ls = m + logf(s);
    out[(size_t)row * OUT_C + lane] = v0 - ls;
    if (lane < OUT_C - 32)
        out[(size_t)row * OUT_C + 32 + lane] = v1 - ls;
}

// ------------------------------- launch -------------------------------------
extern "C" void kernel_launch(void* const* d_in, const int* in_sizes, int n_in,
                              void* d_out, int out_size) {
    const float* x    = (const float*)d_in[0];
    const int*   erow = (const int*)d_in[1];
    const int*   ecol = (const int*)d_in[2];
    const float* ew   = (const float*)d_in[3];
    const float* W1   = (const float*)d_in[4];
    const float* b1   = (const float*)d_in[5];
    const float* W2   = (const float*)d_in[6];
    const float* b2   = (const float*)d_in[7];
    float* out = (float*)d_out;

    // CSR build
    zero_deg_kernel<<<(N_NODES + 255) / 256, 256>>>();
    hist_kernel<<<(N_EDGES + 255) / 256, 256>>>(erow);
    scan_kernel<<<1, 1024>>>();
    scatter_kernel<<<(N_EDGES + 255) / 256, 256>>>(erow, ecol, ew);

    // Fused MLP (both layers): writes g_x0 and g_hA directly
    cudaFuncSetAttribute(mlp_fused_kernel,
                         cudaFuncAttributeMaxDynamicSharedMemorySize, FUSED_SMEM);
    mlp_fused_kernel<<<(N_NODES + 63) / 64, 256, FUSED_SMEM>>>(x, W1, b1, W2, b2);

    // 10 propagation rounds (device-side ping-pong)
    const int spmm_blocks = (N_NODES * 32 + 255) / 256;
    for (int it = 0; it < NUM_LAYERS; it++)
        spmm_kernel<<<spmm_blocks, 256>>>(it & 1);

    lsm_kernel<<<spmm_blocks, 256>>>(out);
}